// round 1
// baseline (speedup 1.0000x reference)
#include <cuda_runtime.h>

// ---------------- problem constants ----------------
#define BB   8
#define NN   1024
#define FIN  64
#define CH1  256       // HID
#define CH2  128       // OUT
#define NH   4
#define DD1  64        // CH1/NH
#define DD2  32        // CH2/NH
#define NEG  0.2f

// ---------------- scratch (device globals; no allocation allowed) ----------------
__device__ __align__(16) float g_ne[NN * CH1];          // normalized embed
__device__ unsigned char       g_adjmask[NN * NN];      // mask bytes
__device__ int                 g_deg[NN];
__device__ int                 g_nbr[NN * NN];          // per-row neighbor lists
__device__ __align__(16) float g_h0[BB * NN * CH1];
__device__ __align__(16) float g_h1[BB * NN * CH1];
__device__ __align__(16) float g_att1[BB * NN * CH1];
__device__ __align__(16) float g_h2[BB * NN * CH2];
__device__ float g_src1[BB * NN * NH], g_dst1[BB * NN * NH];
__device__ float g_src2[BB * NN * NH], g_dst2[BB * NN * NH];

__device__ __forceinline__ float lrelu(float x) { return x > 0.f ? x : NEG * x; }

// ---------------- 1) row-normalize embed ----------------
__global__ void norm_kernel(const float* __restrict__ embed) {
    int i = blockIdx.x, t = threadIdx.x;           // 256 threads, CH1 elems/row
    float v = embed[i * CH1 + t];
    __shared__ float red[CH1];
    red[t] = v * v;
    __syncthreads();
    for (int s = CH1 / 2; s > 0; s >>= 1) {
        if (t < s) red[t] += red[t + s];
        __syncthreads();
    }
    g_ne[i * CH1 + t] = v * rsqrtf(red[0]);
}

// ---------------- 2) adjacency mask: (ne @ ne^T) > 0.5 ----------------
// 64x64 tile per block, 256 threads, 4x4 per thread, K = CH1
__global__ void adj_kernel() {
    __shared__ float As[16][68];
    __shared__ float Bs[16][68];
    int row0 = blockIdx.y * 64, col0 = blockIdx.x * 64;
    int t = threadIdx.x;
    int tx = t & 15, ty = t >> 4;
    int lrow = t >> 2, lc4 = (t & 3) * 4;

    float acc[4][4];
#pragma unroll
    for (int i = 0; i < 4; i++)
#pragma unroll
        for (int j = 0; j < 4; j++) acc[i][j] = 0.f;

    for (int k0 = 0; k0 < CH1; k0 += 16) {
        float4 a = *(const float4*)&g_ne[(row0 + lrow) * CH1 + k0 + lc4];
        float4 b = *(const float4*)&g_ne[(col0 + lrow) * CH1 + k0 + lc4];
        As[lc4 + 0][lrow] = a.x; As[lc4 + 1][lrow] = a.y;
        As[lc4 + 2][lrow] = a.z; As[lc4 + 3][lrow] = a.w;
        Bs[lc4 + 0][lrow] = b.x; Bs[lc4 + 1][lrow] = b.y;
        Bs[lc4 + 2][lrow] = b.z; Bs[lc4 + 3][lrow] = b.w;
        __syncthreads();
#pragma unroll
        for (int k = 0; k < 16; k++) {
            float4 av = *(const float4*)&As[k][ty * 4];
            float4 bv = *(const float4*)&Bs[k][tx * 4];
            float ar[4] = {av.x, av.y, av.z, av.w};
            float br[4] = {bv.x, bv.y, bv.z, bv.w};
#pragma unroll
            for (int i = 0; i < 4; i++)
#pragma unroll
                for (int j = 0; j < 4; j++) acc[i][j] = fmaf(ar[i], br[j], acc[i][j]);
        }
        __syncthreads();
    }
#pragma unroll
    for (int i = 0; i < 4; i++)
#pragma unroll
        for (int j = 0; j < 4; j++)
            g_adjmask[(row0 + ty * 4 + i) * NN + col0 + tx * 4 + j] =
                (acc[i][j] > 0.5f) ? 1 : 0;
}

// ---------------- 3) compact mask rows into ordered neighbor lists ----------------
__global__ void compact_kernel() {
    int i = blockIdx.x, t = threadIdx.x;       // 256 threads
    __shared__ int sc[256];
    __shared__ int base;
    if (t == 0) base = 0;
    __syncthreads();
    for (int c = 0; c < NN / 256; c++) {
        int j = c * 256 + t;
        int f = g_adjmask[i * NN + j];
        sc[t] = f;
        __syncthreads();
        // inclusive Hillis-Steele scan
        for (int off = 1; off < 256; off <<= 1) {
            int v = sc[t];
            int add = (t >= off) ? sc[t - off] : 0;
            __syncthreads();
            sc[t] = v + add;
            __syncthreads();
        }
        int incl = sc[t];
        if (f) g_nbr[i * NN + base + incl - 1] = j;
        __syncthreads();
        if (t == 255) base += incl;
        __syncthreads();
    }
    if (t == 0) g_deg[i] = base;
}

// ---------------- generic tiled GEMM: C[M,Nc] = A[M,K] @ B[K,Nc] (+bias) ----------------
// 64x64 tile, BK=16, 256 threads, 4x4 per thread. M,Nc multiples of 64, K of 16.
template <int K, bool BIAS>
__global__ void gemm_kernel(const float* __restrict__ A, const float* __restrict__ Bm,
                            const float* __restrict__ bias, float* __restrict__ C,
                            int Nc) {
    __shared__ float As[16][68];
    __shared__ float Bs[16][68];
    int row0 = blockIdx.y * 64, col0 = blockIdx.x * 64;
    int t = threadIdx.x;
    int tx = t & 15, ty = t >> 4;
    int arow = t >> 2, ac4 = (t & 3) * 4;      // A tile loader mapping
    int brow = t >> 4, bc4 = (t & 15) * 4;     // B tile loader mapping

    float acc[4][4];
#pragma unroll
    for (int i = 0; i < 4; i++)
#pragma unroll
        for (int j = 0; j < 4; j++) acc[i][j] = 0.f;

    for (int k0 = 0; k0 < K; k0 += 16) {
        float4 a = *(const float4*)&A[(row0 + arow) * K + k0 + ac4];
        As[ac4 + 0][arow] = a.x; As[ac4 + 1][arow] = a.y;
        As[ac4 + 2][arow] = a.z; As[ac4 + 3][arow] = a.w;
        float4 b = *(const float4*)&Bm[(k0 + brow) * Nc + col0 + bc4];
        *(float4*)&Bs[brow][bc4] = b;
        __syncthreads();
#pragma unroll
        for (int k = 0; k < 16; k++) {
            float4 av = *(const float4*)&As[k][ty * 4];
            float4 bv = *(const float4*)&Bs[k][tx * 4];
            float ar[4] = {av.x, av.y, av.z, av.w};
            float br[4] = {bv.x, bv.y, bv.z, bv.w};
#pragma unroll
            for (int i = 0; i < 4; i++)
#pragma unroll
                for (int j = 0; j < 4; j++) acc[i][j] = fmaf(ar[i], br[j], acc[i][j]);
        }
        __syncthreads();
    }
#pragma unroll
    for (int i = 0; i < 4; i++) {
        int r = row0 + ty * 4 + i;
#pragma unroll
        for (int j = 0; j < 4; j++) {
            int cc = col0 + tx * 4 + j;
            float v = acc[i][j];
            if (BIAS) v += bias[cc];
            C[r * Nc + cc] = v;
        }
    }
}

// ---------------- per-(b,n) attention coefficients: src/dst dot products ----------------
template <int C, int D>
__global__ void attn_coef_kernel(const float* __restrict__ h,
                                 const float* __restrict__ a_src,
                                 const float* __restrict__ a_dst,
                                 float* __restrict__ gs, float* __restrict__ gd) {
    int bn = blockIdx.x, t = threadIdx.x;      // C threads
    __shared__ float ss[C], sd[C];
    float hv = h[bn * C + t];
    ss[t] = hv * a_src[t];
    sd[t] = hv * a_dst[t];
    __syncthreads();
    for (int s = D / 2; s > 0; s >>= 1) {
        if ((t & (D - 1)) < s) { ss[t] += ss[t + s]; sd[t] += sd[t + s]; }
        __syncthreads();
    }
    if ((t & (D - 1)) == 0) {
        int hh = t / D;
        gs[bn * NH + hh] = ss[t];
        gd[bn * NH + hh] = sd[t];
    }
}

// ---------------- sparse GAT attention over neighbor lists ----------------
template <int C, int D, bool RELU>
__global__ void attn_kernel(const float* __restrict__ hin,
                            const float* __restrict__ gsrc,
                            const float* __restrict__ gdst,
                            const float* __restrict__ bias,
                            float* __restrict__ out) {
    int bn = blockIdx.x;
    int b = bn >> 10, i = bn & (NN - 1);
    int t = threadIdx.x;                        // C threads
    int hd = t / D;
    int deg = g_deg[i];
    const int* nb = &g_nbr[i * NN];

    __shared__ float sm[NH], sz[NH];
    int w = t >> 5, lane = t & 31;
    if (w < NH) {
        float adst = gdst[bn * NH + w];
        float mm = -3e38f;
        for (int k = lane; k < deg; k += 32) {
            int j = nb[k];
            float e = lrelu(adst + gsrc[(b * NN + j) * NH + w]);
            mm = fmaxf(mm, e);
        }
#pragma unroll
        for (int o = 16; o; o >>= 1) mm = fmaxf(mm, __shfl_xor_sync(0xffffffffu, mm, o));
        float zz = 0.f;
        for (int k = lane; k < deg; k += 32) {
            int j = nb[k];
            float e = lrelu(adst + gsrc[(b * NN + j) * NH + w]);
            zz += __expf(e - mm);
        }
#pragma unroll
        for (int o = 16; o; o >>= 1) zz += __shfl_xor_sync(0xffffffffu, zz, o);
        if (lane == 0) { sm[w] = mm; sz[w] = zz; }
    }
    __syncthreads();

    float adst = gdst[bn * NH + hd];
    float mh = sm[hd];
    float invZ = 1.0f / sz[hd];
    float acc = 0.f;
    for (int k = 0; k < deg; k++) {
        int j = nb[k];
        float e = lrelu(adst + gsrc[(b * NN + j) * NH + hd]);
        float wt = __expf(e - mh) * invZ;
        acc = fmaf(wt, hin[(b * NN + j) * C + t], acc);
    }
    float o = acc + bias[t];
    out[bn * C + t] = RELU ? fmaxf(o, 0.f) : o;
}

// ---------------- launcher ----------------
extern "C" void kernel_launch(void* const* d_in, const int* in_sizes, int n_in,
                              void* d_out, int out_size) {
    const float* x      = (const float*)d_in[0];
    const float* embed  = (const float*)d_in[1];
    const float* Wp     = (const float*)d_in[2];
    const float* bp     = (const float*)d_in[3];
    const float* W1     = (const float*)d_in[4];
    const float* a_src1 = (const float*)d_in[5];
    const float* a_dst1 = (const float*)d_in[6];
    const float* b1     = (const float*)d_in[7];
    const float* W2     = (const float*)d_in[8];
    const float* a_src2 = (const float*)d_in[9];
    const float* a_dst2 = (const float*)d_in[10];
    const float* b2     = (const float*)d_in[11];
    float* out = (float*)d_out;

    float *p_h0, *p_h1, *p_att1, *p_h2, *p_s1, *p_d1, *p_s2, *p_d2;
    cudaGetSymbolAddress((void**)&p_h0,   g_h0);
    cudaGetSymbolAddress((void**)&p_h1,   g_h1);
    cudaGetSymbolAddress((void**)&p_att1, g_att1);
    cudaGetSymbolAddress((void**)&p_h2,   g_h2);
    cudaGetSymbolAddress((void**)&p_s1,   g_src1);
    cudaGetSymbolAddress((void**)&p_d1,   g_dst1);
    cudaGetSymbolAddress((void**)&p_s2,   g_src2);
    cudaGetSymbolAddress((void**)&p_d2,   g_dst2);

    // adjacency pipeline (batch-independent)
    norm_kernel<<<NN, CH1>>>(embed);
    adj_kernel<<<dim3(NN / 64, NN / 64), 256>>>();
    compact_kernel<<<NN, 256>>>();

    // h0 = x @ Wp + bp         [8192,64]@[64,256]
    gemm_kernel<FIN, true><<<dim3(CH1 / 64, BB * NN / 64), 256>>>(x, Wp, bp, p_h0, CH1);
    // h1 = h0 @ W1             [8192,256]@[256,256]
    gemm_kernel<CH1, false><<<dim3(CH1 / 64, BB * NN / 64), 256>>>(p_h0, W1, nullptr, p_h1, CH1);
    // attention layer 1 (relu epilogue, +b1)
    attn_coef_kernel<CH1, DD1><<<BB * NN, CH1>>>(p_h1, a_src1, a_dst1, p_s1, p_d1);
    attn_kernel<CH1, DD1, true><<<BB * NN, CH1>>>(p_h1, p_s1, p_d1, b1, p_att1);
    // h2 = att1 @ W2           [8192,256]@[256,128]
    gemm_kernel<CH1, false><<<dim3(CH2 / 64, BB * NN / 64), 256>>>(p_att1, W2, nullptr, p_h2, CH2);
    // attention layer 2 (+b2) -> output
    attn_coef_kernel<CH2, DD2><<<BB * NN, CH2>>>(p_h2, a_src2, a_dst2, p_s2, p_d2);
    attn_kernel<CH2, DD2, false><<<BB * NN, CH2>>>(p_h2, p_s2, p_d2, b2, out);
}

// round 2
// speedup vs baseline: 1.1437x; 1.1437x over previous
#include <cuda_runtime.h>

// ---------------- problem constants ----------------
#define BB   8
#define NN   1024
#define FIN  64
#define CH1  256       // HID
#define CH2  128       // OUT
#define NH   4
#define DD1  64        // CH1/NH
#define DD2  32        // CH2/NH
#define NEG  0.2f

// ---------------- scratch (device globals; no allocation allowed) ----------------
__device__ __align__(16) float g_ne[NN * CH1];          // normalized embed
__device__ unsigned char       g_adjmask[NN * NN];      // mask bytes
__device__ int                 g_deg[NN];
__device__ int                 g_nbr[NN * NN];          // per-row neighbor lists
__device__ __align__(16) float g_h0[BB * NN * CH1];
__device__ __align__(16) float g_h1[BB * NN * CH1];
__device__ __align__(16) float g_att1[BB * NN * CH1];
__device__ __align__(16) float g_h2[BB * NN * CH2];
__device__ float g_src1[BB * NN * NH], g_dst1[BB * NN * NH];
__device__ float g_src2[BB * NN * NH], g_dst2[BB * NN * NH];

__device__ __forceinline__ float lrelu(float x) { return x > 0.f ? x : NEG * x; }

// ---------------- 1) row-normalize embed (warp shuffles) ----------------
__global__ void norm_kernel(const float* __restrict__ embed) {
    int i = blockIdx.x, t = threadIdx.x;           // 256 threads
    float v = embed[i * CH1 + t];
    float s = v * v;
#pragma unroll
    for (int o = 16; o; o >>= 1) s += __shfl_xor_sync(0xffffffffu, s, o);
    __shared__ float ws[8];
    int w = t >> 5, lane = t & 31;
    if (lane == 0) ws[w] = s;
    __syncthreads();
    if (w == 0) {
        float x = (lane < 8) ? ws[lane] : 0.f;
#pragma unroll
        for (int o = 4; o; o >>= 1) x += __shfl_xor_sync(0xffffffffu, x, o);
        if (lane == 0) ws[0] = rsqrtf(x);
    }
    __syncthreads();
    g_ne[i * CH1 + t] = v * ws[0];
}

// ---------------- tiled GEMM: 128xBN tile, BK=16, 256 threads, 8x(BN/16)/thread ----
// C[M,Nc] = A[M,K] @ B (B row-major [K,Nc], or TRANSB: B[j,k] row-major, used as B^T)
// MASKOUT: write (acc > 0.5) bytes into Cmask instead of floats.
template <int K, int BN, bool TRANSB, bool BIAS, bool MASKOUT>
__launch_bounds__(256)
__global__ void gemm2(const float* __restrict__ A, const float* __restrict__ Bm,
                      const float* __restrict__ bias, float* __restrict__ C,
                      unsigned char* __restrict__ Cmask, int Nc) {
    constexpr int BKK = 16;
    constexpr int TN  = BN / 16;      // 8 or 4
    constexpr int BL  = BN / 64;      // float4 B-loads per thread (2 or 1)
    __shared__ float As[2][BKK][128 + 4];
    __shared__ float Bs[2][BKK][BN + 4];

    const int t = threadIdx.x;
    const int row0 = blockIdx.y * 128;
    const int col0 = blockIdx.x * BN;
    const int ty = t >> 4, tx = t & 15;

    float regA[2][4];
    float regB[BL][4];
    float acc[8][TN];
#pragma unroll
    for (int i = 0; i < 8; i++)
#pragma unroll
        for (int j = 0; j < TN; j++) acc[i][j] = 0.f;

    auto loadA = [&](int k0) {
#pragma unroll
        for (int l = 0; l < 2; l++) {
            int idx = l * 256 + t;
            int r = idx >> 2, c4 = (idx & 3) * 4;
            float4 v = *(const float4*)&A[(row0 + r) * K + k0 + c4];
            regA[l][0] = v.x; regA[l][1] = v.y; regA[l][2] = v.z; regA[l][3] = v.w;
        }
    };
    auto storeA = [&](int buf) {
#pragma unroll
        for (int l = 0; l < 2; l++) {
            int idx = l * 256 + t;
            int r = idx >> 2, c4 = (idx & 3) * 4;
#pragma unroll
            for (int i = 0; i < 4; i++) As[buf][c4 + i][r] = regA[l][i];
        }
    };
    auto loadB = [&](int k0) {
#pragma unroll
        for (int l = 0; l < BL; l++) {
            int idx = l * 256 + t;
            if (TRANSB) {
                int col = idx >> 2, k4 = (idx & 3) * 4;
                float4 v = *(const float4*)&Bm[(col0 + col) * K + k0 + k4];
                regB[l][0] = v.x; regB[l][1] = v.y; regB[l][2] = v.z; regB[l][3] = v.w;
            } else {
                int row = idx / (BN / 4), c4 = (idx % (BN / 4)) * 4;
                float4 v = *(const float4*)&Bm[(k0 + row) * Nc + col0 + c4];
                regB[l][0] = v.x; regB[l][1] = v.y; regB[l][2] = v.z; regB[l][3] = v.w;
            }
        }
    };
    auto storeB = [&](int buf) {
#pragma unroll
        for (int l = 0; l < BL; l++) {
            int idx = l * 256 + t;
            if (TRANSB) {
                int col = idx >> 2, k4 = (idx & 3) * 4;
#pragma unroll
                for (int i = 0; i < 4; i++) Bs[buf][k4 + i][col] = regB[l][i];
            } else {
                int row = idx / (BN / 4), c4 = (idx % (BN / 4)) * 4;
                *(float4*)&Bs[buf][row][c4] =
                    make_float4(regB[l][0], regB[l][1], regB[l][2], regB[l][3]);
            }
        }
    };
    auto compute = [&](int buf) {
#pragma unroll
        for (int k = 0; k < BKK; k++) {
            float a[8], b[TN];
            *(float4*)a       = *(const float4*)&As[buf][k][ty * 8];
            *(float4*)(a + 4) = *(const float4*)&As[buf][k][ty * 8 + 4];
#pragma unroll
            for (int j = 0; j < TN; j += 4)
                *(float4*)(b + j) = *(const float4*)&Bs[buf][k][tx * TN + j];
#pragma unroll
            for (int i = 0; i < 8; i++)
#pragma unroll
                for (int j = 0; j < TN; j++)
                    acc[i][j] = fmaf(a[i], b[j], acc[i][j]);
        }
    };

    loadA(0); loadB(0);
    storeA(0); storeB(0);
    __syncthreads();
    int buf = 0;
    for (int k0 = BKK; k0 < K; k0 += BKK) {
        loadA(k0); loadB(k0);
        compute(buf);
        storeA(buf ^ 1); storeB(buf ^ 1);
        __syncthreads();
        buf ^= 1;
    }
    compute(buf);

    if (MASKOUT) {
#pragma unroll
        for (int i = 0; i < 8; i++) {
            int r = row0 + ty * 8 + i;
#pragma unroll
            for (int j = 0; j < TN; j++)
                Cmask[r * Nc + col0 + tx * TN + j] = (acc[i][j] > 0.5f) ? 1 : 0;
        }
    } else {
        float bv[TN];
        if (BIAS) {
#pragma unroll
            for (int j = 0; j < TN; j++) bv[j] = bias[col0 + tx * TN + j];
        }
#pragma unroll
        for (int i = 0; i < 8; i++) {
            int r = row0 + ty * 8 + i;
#pragma unroll
            for (int j = 0; j < TN; j += 4) {
                float4 v;
                v.x = acc[i][j + 0]; v.y = acc[i][j + 1];
                v.z = acc[i][j + 2]; v.w = acc[i][j + 3];
                if (BIAS) { v.x += bv[j]; v.y += bv[j + 1]; v.z += bv[j + 2]; v.w += bv[j + 3]; }
                *(float4*)&C[r * Nc + col0 + tx * TN + j] = v;
            }
        }
    }
}

// ---------------- 3) compact mask rows -> neighbor lists (warp ballot scan) ------
__global__ void compact_kernel() {
    int gw = (blockIdx.x * blockDim.x + threadIdx.x) >> 5;   // warp id = row
    int lane = threadIdx.x & 31;
    if (gw >= NN) return;
    const uchar4* row = (const uchar4*)&g_adjmask[gw * NN];
    int* dst = &g_nbr[gw * NN];
    int base = 0;
#pragma unroll
    for (int c = 0; c < NN / 128; c++) {
        uchar4 v = row[c * 32 + lane];
        int cnt = (int)v.x + v.y + v.z + v.w;
        int sc = cnt;
#pragma unroll
        for (int o = 1; o < 32; o <<= 1) {
            int n = __shfl_up_sync(0xffffffffu, sc, o);
            if (lane >= o) sc += n;
        }
        int pos = base + sc - cnt;
        int col = (c * 32 + lane) * 4;
        if (v.x) dst[pos++] = col;
        if (v.y) dst[pos++] = col + 1;
        if (v.z) dst[pos++] = col + 2;
        if (v.w) dst[pos++] = col + 3;
        base += __shfl_sync(0xffffffffu, sc, 31);
    }
    if (lane == 0) g_deg[gw] = base;
}

// ---------------- per-(b,n) attention coefficients ----------------
template <int C, int D>
__global__ void attn_coef_kernel(const float* __restrict__ h,
                                 const float* __restrict__ a_src,
                                 const float* __restrict__ a_dst,
                                 float* __restrict__ gs, float* __restrict__ gd) {
    int bn = blockIdx.x, t = threadIdx.x;      // C threads
    __shared__ float ss[C], sd[C];
    float hv = h[bn * C + t];
    ss[t] = hv * a_src[t];
    sd[t] = hv * a_dst[t];
    __syncthreads();
    for (int s = D / 2; s > 0; s >>= 1) {
        if ((t & (D - 1)) < s) { ss[t] += ss[t + s]; sd[t] += sd[t + s]; }
        __syncthreads();
    }
    if ((t & (D - 1)) == 0) {
        int hh = t / D;
        gs[bn * NH + hh] = ss[t];
        gd[bn * NH + hh] = sd[t];
    }
}

// ---------------- sparse GAT attention over neighbor lists ----------------
template <int C, int D, bool RELU>
__global__ void attn_kernel(const float* __restrict__ hin,
                            const float* __restrict__ gsrc,
                            const float* __restrict__ gdst,
                            const float* __restrict__ bias,
                            float* __restrict__ out) {
    int bn = blockIdx.x;
    int b = bn >> 10, i = bn & (NN - 1);
    int t = threadIdx.x;                        // C threads
    int hd = t / D;
    int deg = g_deg[i];
    const int* nb = &g_nbr[i * NN];

    __shared__ float sm[NH], sz[NH];
    int w = t >> 5, lane = t & 31;
    if (w < NH) {
        float adst = gdst[bn * NH + w];
        float mm = -3e38f;
        for (int k = lane; k < deg; k += 32) {
            int j = nb[k];
            float e = lrelu(adst + gsrc[(b * NN + j) * NH + w]);
            mm = fmaxf(mm, e);
        }
#pragma unroll
        for (int o = 16; o; o >>= 1) mm = fmaxf(mm, __shfl_xor_sync(0xffffffffu, mm, o));
        float zz = 0.f;
        for (int k = lane; k < deg; k += 32) {
            int j = nb[k];
            float e = lrelu(adst + gsrc[(b * NN + j) * NH + w]);
            zz += __expf(e - mm);
        }
#pragma unroll
        for (int o = 16; o; o >>= 1) zz += __shfl_xor_sync(0xffffffffu, zz, o);
        if (lane == 0) { sm[w] = mm; sz[w] = zz; }
    }
    __syncthreads();

    float adst = gdst[bn * NH + hd];
    float mh = sm[hd];
    float invZ = 1.0f / sz[hd];
    float acc = 0.f;
    for (int k = 0; k < deg; k++) {
        int j = nb[k];
        float e = lrelu(adst + gsrc[(b * NN + j) * NH + hd]);
        float wt = __expf(e - mh) * invZ;
        acc = fmaf(wt, hin[(b * NN + j) * C + t], acc);
    }
    float o = acc + bias[t];
    out[bn * C + t] = RELU ? fmaxf(o, 0.f) : o;
}

// ---------------- launcher ----------------
extern "C" void kernel_launch(void* const* d_in, const int* in_sizes, int n_in,
                              void* d_out, int out_size) {
    const float* x      = (const float*)d_in[0];
    const float* embed  = (const float*)d_in[1];
    const float* Wp     = (const float*)d_in[2];
    const float* bp     = (const float*)d_in[3];
    const float* W1     = (const float*)d_in[4];
    const float* a_src1 = (const float*)d_in[5];
    const float* a_dst1 = (const float*)d_in[6];
    const float* b1     = (const float*)d_in[7];
    const float* W2     = (const float*)d_in[8];
    const float* a_src2 = (const float*)d_in[9];
    const float* a_dst2 = (const float*)d_in[10];
    const float* b2     = (const float*)d_in[11];
    float* out = (float*)d_out;

    float *p_ne, *p_h0, *p_h1, *p_att1, *p_h2, *p_s1, *p_d1, *p_s2, *p_d2;
    unsigned char* p_mask;
    cudaGetSymbolAddress((void**)&p_ne,   g_ne);
    cudaGetSymbolAddress((void**)&p_mask, g_adjmask);
    cudaGetSymbolAddress((void**)&p_h0,   g_h0);
    cudaGetSymbolAddress((void**)&p_h1,   g_h1);
    cudaGetSymbolAddress((void**)&p_att1, g_att1);
    cudaGetSymbolAddress((void**)&p_h2,   g_h2);
    cudaGetSymbolAddress((void**)&p_s1,   g_src1);
    cudaGetSymbolAddress((void**)&p_d1,   g_dst1);
    cudaGetSymbolAddress((void**)&p_s2,   g_src2);
    cudaGetSymbolAddress((void**)&p_d2,   g_dst2);

    // adjacency pipeline (batch-independent)
    norm_kernel<<<NN, CH1>>>(embed);
    // mask = (ne @ ne^T) > 0.5 : TRANSB + mask-output GEMM, 128x64 tiles, 128 blocks
    gemm2<CH1, 64, true, false, true>
        <<<dim3(NN / 64, NN / 128), 256>>>(p_ne, p_ne, nullptr, nullptr, p_mask, NN);
    compact_kernel<<<NN / 8, 256>>>();

    // h0 = x @ Wp + bp         [8192,64]@[64,256]
    gemm2<FIN, 128, false, true, false>
        <<<dim3(CH1 / 128, BB * NN / 128), 256>>>(x, Wp, bp, p_h0, nullptr, CH1);
    // h1 = h0 @ W1             [8192,256]@[256,256]
    gemm2<CH1, 128, false, false, false>
        <<<dim3(CH1 / 128, BB * NN / 128), 256>>>(p_h0, W1, nullptr, p_h1, nullptr, CH1);
    // attention layer 1 (relu epilogue, +b1)
    attn_coef_kernel<CH1, DD1><<<BB * NN, CH1>>>(p_h1, a_src1, a_dst1, p_s1, p_d1);
    attn_kernel<CH1, DD1, true><<<BB * NN, CH1>>>(p_h1, p_s1, p_d1, b1, p_att1);
    // h2 = att1 @ W2           [8192,256]@[256,128] : BN=64 -> 128 blocks
    gemm2<CH1, 64, false, false, false>
        <<<dim3(CH2 / 64, BB * NN / 128), 256>>>(p_att1, W2, nullptr, p_h2, nullptr, CH2);
    // attention layer 2 (+b2) -> output
    attn_coef_kernel<CH2, DD2><<<BB * NN, CH2>>>(p_h2, a_src2, a_dst2, p_s2, p_d2);
    attn_kernel<CH2, DD2, false><<<BB * NN, CH2>>>(p_h2, p_s2, p_d2, b2, out);
}

// round 3
// speedup vs baseline: 1.1621x; 1.0161x over previous
#include <cuda_runtime.h>

// ---------------- problem constants ----------------
#define BB   8
#define NN   1024
#define FIN  64
#define CH1  256       // HID
#define CH2  128       // OUT
#define NH   4
#define DD1  64        // CH1/NH
#define DD2  32        // CH2/NH
#define NEG  0.2f

// ---------------- scratch (device globals; no allocation allowed) ----------------
__device__ __align__(16) float g_ne[NN * CH1];          // normalized embed
__device__ unsigned char       g_adjmask[NN * NN];      // mask bytes
__device__ int                 g_deg[NN];
__device__ int                 g_nbr[NN * NN];          // per-row neighbor lists
__device__ __align__(16) float g_Wf[FIN * CH1];         // Wp @ W1
__device__ __align__(16) float g_bf[CH1];               // bp @ W1
__device__ __align__(16) float g_h1[BB * NN * CH1];
__device__ __align__(16) float g_att1[BB * NN * CH1];
__device__ __align__(16) float g_h2[BB * NN * CH2];
__device__ float g_src1[BB * NN * NH], g_dst1[BB * NN * NH];
__device__ float g_src2[BB * NN * NH], g_dst2[BB * NN * NH];

__device__ __forceinline__ float lrelu(float x) { return x > 0.f ? x : NEG * x; }

// ---------------- 1) row-normalize embed (warp shuffles) ----------------
__global__ void norm_kernel(const float* __restrict__ embed) {
    int i = blockIdx.x, t = threadIdx.x;           // 256 threads
    float v = embed[i * CH1 + t];
    float s = v * v;
#pragma unroll
    for (int o = 16; o; o >>= 1) s += __shfl_xor_sync(0xffffffffu, s, o);
    __shared__ float ws[8];
    int w = t >> 5, lane = t & 31;
    if (lane == 0) ws[w] = s;
    __syncthreads();
    if (w == 0) {
        float x = (lane < 8) ? ws[lane] : 0.f;
#pragma unroll
        for (int o = 4; o; o >>= 1) x += __shfl_xor_sync(0xffffffffu, x, o);
        if (lane == 0) ws[0] = rsqrtf(x);
    }
    __syncthreads();
    g_ne[i * CH1 + t] = v * ws[0];
}

// ---------------- fused bias: bf = bp @ W1 ----------------
__global__ void fuseb_kernel(const float* __restrict__ bp, const float* __restrict__ W1,
                             float* __restrict__ bf) {
    int c = threadIdx.x;   // 256 threads, 1 block
    float s = 0.f;
#pragma unroll 8
    for (int k = 0; k < CH1; k++) s = fmaf(bp[k], W1[k * CH1 + c], s);
    bf[c] = s;
}

// ================= unified tiled GEMM =================
// C[M,Nc] = A[M,K] @ B (+bias). BM=64, BN=64, BK=16, 128 threads, 4x8 per thread.
// TRANSB : B given row-major [Nc, K], used as B^T.
// MASKOUT: write (acc > 0.5) bytes into Cmask instead of floats.
// D != 0 : also emit attention coefficients gs/gd: per-row, per-head dots with
//          asrc/adst (flat [Nc] vectors; head = col / D). Requires D in {32,64}.
template <int K, bool TRANSB, bool BIAS, bool MASKOUT, int D>
__launch_bounds__(128)
__global__ void gemm3(const float* __restrict__ A, const float* __restrict__ Bm,
                      const float* __restrict__ bias, float* __restrict__ C,
                      unsigned char* __restrict__ Cmask,
                      const float* __restrict__ asrc, const float* __restrict__ adst,
                      float* __restrict__ gs, float* __restrict__ gd, int Nc) {
    constexpr int BK = 16;
    __shared__ float As[2][BK][68];   // [k][row], 68-stride (16B aligned)
    __shared__ float Bs[2][BK][68];   // [k][col]

    const int t = threadIdx.x;
    const int row0 = blockIdx.y * 64;
    const int col0 = blockIdx.x * 64;
    const int ty = t >> 3;            // 0..15 -> 4 rows each
    const int tx = t & 7;             // 0..7  -> 8 cols each

    float regA[2][4], regB[2][4];
    float acc[4][8];
#pragma unroll
    for (int i = 0; i < 4; i++)
#pragma unroll
        for (int j = 0; j < 8; j++) acc[i][j] = 0.f;

    auto loadA = [&](int k0) {
#pragma unroll
        for (int l = 0; l < 2; l++) {
            int idx = l * 128 + t;
            int r = idx >> 2, c4 = (idx & 3) * 4;
            float4 v = *(const float4*)&A[(row0 + r) * K + k0 + c4];
            regA[l][0] = v.x; regA[l][1] = v.y; regA[l][2] = v.z; regA[l][3] = v.w;
        }
    };
    auto storeA = [&](int buf) {
#pragma unroll
        for (int l = 0; l < 2; l++) {
            int idx = l * 128 + t;
            int r = idx >> 2, c4 = (idx & 3) * 4;
#pragma unroll
            for (int i = 0; i < 4; i++) As[buf][c4 + i][r] = regA[l][i];
        }
    };
    auto loadB = [&](int k0) {
#pragma unroll
        for (int l = 0; l < 2; l++) {
            int idx = l * 128 + t;
            if (TRANSB) {
                int col = idx >> 2, k4 = (idx & 3) * 4;
                float4 v = *(const float4*)&Bm[(col0 + col) * K + k0 + k4];
                regB[l][0] = v.x; regB[l][1] = v.y; regB[l][2] = v.z; regB[l][3] = v.w;
            } else {
                int row = idx >> 4, c4 = (idx & 15) * 4;
                float4 v = *(const float4*)&Bm[(k0 + row) * Nc + col0 + c4];
                regB[l][0] = v.x; regB[l][1] = v.y; regB[l][2] = v.z; regB[l][3] = v.w;
            }
        }
    };
    auto storeB = [&](int buf) {
#pragma unroll
        for (int l = 0; l < 2; l++) {
            int idx = l * 128 + t;
            if (TRANSB) {
                int col = idx >> 2, k4 = (idx & 3) * 4;
#pragma unroll
                for (int i = 0; i < 4; i++) Bs[buf][k4 + i][col] = regB[l][i];
            } else {
                int row = idx >> 4, c4 = (idx & 15) * 4;
                *(float4*)&Bs[buf][row][c4] =
                    make_float4(regB[l][0], regB[l][1], regB[l][2], regB[l][3]);
            }
        }
    };
    auto compute = [&](int buf) {
#pragma unroll
        for (int k = 0; k < BK; k++) {
            float a[4], b[8];
            *(float4*)a       = *(const float4*)&As[buf][k][ty * 4];
            *(float4*)(b)     = *(const float4*)&Bs[buf][k][tx * 8];
            *(float4*)(b + 4) = *(const float4*)&Bs[buf][k][tx * 8 + 4];
#pragma unroll
            for (int i = 0; i < 4; i++)
#pragma unroll
                for (int j = 0; j < 8; j++)
                    acc[i][j] = fmaf(a[i], b[j], acc[i][j]);
        }
    };

    loadA(0); loadB(0);
    storeA(0); storeB(0);
    __syncthreads();
    int buf = 0;
    for (int k0 = BK; k0 < K; k0 += BK) {
        loadA(k0); loadB(k0);
        compute(buf);
        storeA(buf ^ 1); storeB(buf ^ 1);
        __syncthreads();
        buf ^= 1;
    }
    compute(buf);

    if (MASKOUT) {
#pragma unroll
        for (int i = 0; i < 4; i++) {
            int r = row0 + ty * 4 + i;
#pragma unroll
            for (int j = 0; j < 8; j++)
                Cmask[r * Nc + col0 + tx * 8 + j] = (acc[i][j] > 0.5f) ? 1 : 0;
        }
        return;
    }

    float bv[8];
    if (BIAS) {
#pragma unroll
        for (int j = 0; j < 8; j++) bv[j] = bias[col0 + tx * 8 + j];
    }
#pragma unroll
    for (int i = 0; i < 4; i++) {
#pragma unroll
        for (int j = 0; j < 8; j++) if (BIAS) acc[i][j] += bv[j];
        int r = row0 + ty * 4 + i;
        float4 v0 = make_float4(acc[i][0], acc[i][1], acc[i][2], acc[i][3]);
        float4 v1 = make_float4(acc[i][4], acc[i][5], acc[i][6], acc[i][7]);
        *(float4*)&C[r * Nc + col0 + tx * 8]     = v0;
        *(float4*)&C[r * Nc + col0 + tx * 8 + 4] = v1;
    }

    if (D) {
        // attention coefficient epilogue: head = global_col / D (constant per thread)
        const int gc0 = col0 + tx * 8;
        const int head = gc0 / D;
        float sa[8], sd[8];
#pragma unroll
        for (int j = 0; j < 8; j++) { sa[j] = asrc[gc0 + j]; sd[j] = adst[gc0 + j]; }
        float ps[4], pd[4];
#pragma unroll
        for (int i = 0; i < 4; i++) {
            float s1 = 0.f, s2 = 0.f;
#pragma unroll
            for (int j = 0; j < 8; j++) {
                s1 = fmaf(acc[i][j], sa[j], s1);
                s2 = fmaf(acc[i][j], sd[j], s2);
            }
            ps[i] = s1; pd[i] = s2;
        }
        constexpr int RED = D / 8;   // lanes (tx) per head: 8 for D=64, 4 for D=32
#pragma unroll
        for (int o = RED / 2; o; o >>= 1) {
#pragma unroll
            for (int i = 0; i < 4; i++) {
                ps[i] += __shfl_xor_sync(0xffffffffu, ps[i], o);
                pd[i] += __shfl_xor_sync(0xffffffffu, pd[i], o);
            }
        }
        if ((tx & (RED - 1)) == 0) {
#pragma unroll
            for (int i = 0; i < 4; i++) {
                int r = row0 + ty * 4 + i;
                gs[r * NH + head] = ps[i];
                gd[r * NH + head] = pd[i];
            }
        }
    }
}

// ---------------- 3) compact mask rows -> neighbor lists (warp ballot scan) ------
__global__ void compact_kernel() {
    int gw = (blockIdx.x * blockDim.x + threadIdx.x) >> 5;   // warp id = row
    int lane = threadIdx.x & 31;
    if (gw >= NN) return;
    const uchar4* row = (const uchar4*)&g_adjmask[gw * NN];
    int* dst = &g_nbr[gw * NN];
    int base = 0;
#pragma unroll
    for (int c = 0; c < NN / 128; c++) {
        uchar4 v = row[c * 32 + lane];
        int cnt = (int)v.x + v.y + v.z + v.w;
        int sc = cnt;
#pragma unroll
        for (int o = 1; o < 32; o <<= 1) {
            int n = __shfl_up_sync(0xffffffffu, sc, o);
            if (lane >= o) sc += n;
        }
        int pos = base + sc - cnt;
        int col = (c * 32 + lane) * 4;
        if (v.x) dst[pos++] = col;
        if (v.y) dst[pos++] = col + 1;
        if (v.z) dst[pos++] = col + 2;
        if (v.w) dst[pos++] = col + 3;
        base += __shfl_sync(0xffffffffu, sc, 31);
    }
    if (lane == 0) g_deg[gw] = base;
}

// ---------------- sparse GAT attention over neighbor lists ----------------
template <int C, int D, bool RELU>
__global__ void attn_kernel(const float* __restrict__ hin,
                            const float* __restrict__ gsrc,
                            const float* __restrict__ gdst,
                            const float* __restrict__ bias,
                            float* __restrict__ out) {
    int bn = blockIdx.x;
    int b = bn >> 10, i = bn & (NN - 1);
    int t = threadIdx.x;                        // C threads
    int hd = t / D;
    int deg = g_deg[i];
    const int* nb = &g_nbr[i * NN];

    __shared__ float sm[NH], sz[NH];
    int w = t >> 5, lane = t & 31;
    if (w < NH) {
        float adst = gdst[bn * NH + w];
        float mm = -3e38f;
        for (int k = lane; k < deg; k += 32) {
            int j = nb[k];
            float e = lrelu(adst + gsrc[(b * NN + j) * NH + w]);
            mm = fmaxf(mm, e);
        }
#pragma unroll
        for (int o = 16; o; o >>= 1) mm = fmaxf(mm, __shfl_xor_sync(0xffffffffu, mm, o));
        float zz = 0.f;
        for (int k = lane; k < deg; k += 32) {
            int j = nb[k];
            float e = lrelu(adst + gsrc[(b * NN + j) * NH + w]);
            zz += __expf(e - mm);
        }
#pragma unroll
        for (int o = 16; o; o >>= 1) zz += __shfl_xor_sync(0xffffffffu, zz, o);
        if (lane == 0) { sm[w] = mm; sz[w] = zz; }
    }
    __syncthreads();

    float adst = gdst[bn * NH + hd];
    float mh = sm[hd];
    float invZ = 1.0f / sz[hd];
    float acc = 0.f;
    for (int k = 0; k < deg; k++) {
        int j = nb[k];
        float e = lrelu(adst + gsrc[(b * NN + j) * NH + hd]);
        float wt = __expf(e - mh) * invZ;
        acc = fmaf(wt, hin[(b * NN + j) * C + t], acc);
    }
    float o = acc + bias[t];
    out[bn * C + t] = RELU ? fmaxf(o, 0.f) : o;
}

// ---------------- launcher ----------------
extern "C" void kernel_launch(void* const* d_in, const int* in_sizes, int n_in,
                              void* d_out, int out_size) {
    const float* x      = (const float*)d_in[0];
    const float* embed  = (const float*)d_in[1];
    const float* Wp     = (const float*)d_in[2];
    const float* bp     = (const float*)d_in[3];
    const float* W1     = (const float*)d_in[4];
    const float* a_src1 = (const float*)d_in[5];
    const float* a_dst1 = (const float*)d_in[6];
    const float* b1     = (const float*)d_in[7];
    const float* W2     = (const float*)d_in[8];
    const float* a_src2 = (const float*)d_in[9];
    const float* a_dst2 = (const float*)d_in[10];
    const float* b2     = (const float*)d_in[11];
    float* out = (float*)d_out;

    float *p_ne, *p_Wf, *p_bf, *p_h1, *p_att1, *p_h2, *p_s1, *p_d1, *p_s2, *p_d2;
    unsigned char* p_mask;
    cudaGetSymbolAddress((void**)&p_ne,   g_ne);
    cudaGetSymbolAddress((void**)&p_mask, g_adjmask);
    cudaGetSymbolAddress((void**)&p_Wf,   g_Wf);
    cudaGetSymbolAddress((void**)&p_bf,   g_bf);
    cudaGetSymbolAddress((void**)&p_h1,   g_h1);
    cudaGetSymbolAddress((void**)&p_att1, g_att1);
    cudaGetSymbolAddress((void**)&p_h2,   g_h2);
    cudaGetSymbolAddress((void**)&p_s1,   g_src1);
    cudaGetSymbolAddress((void**)&p_d1,   g_dst1);
    cudaGetSymbolAddress((void**)&p_s2,   g_src2);
    cudaGetSymbolAddress((void**)&p_d2,   g_dst2);

    // adjacency pipeline (batch-independent)
    norm_kernel<<<NN, CH1>>>(embed);
    // mask = (ne @ ne^T) > 0.5
    gemm3<CH1, true, false, true, 0><<<dim3(NN / 64, NN / 64), 128>>>(
        p_ne, p_ne, nullptr, nullptr, p_mask, nullptr, nullptr, nullptr, nullptr, NN);
    compact_kernel<<<NN / 8, 256>>>();

    // fused projection weights: Wf = Wp @ W1, bf = bp @ W1
    gemm3<CH1, false, false, false, 0><<<dim3(CH1 / 64, 1), 128>>>(
        Wp, W1, nullptr, p_Wf, nullptr, nullptr, nullptr, nullptr, nullptr, CH1);
    fuseb_kernel<<<1, CH1>>>(bp, W1, p_bf);

    // h1 = x @ Wf + bf   [8192,64]@[64,256], with attn-coef epilogue (D=64)
    gemm3<FIN, false, true, false, DD1><<<dim3(CH1 / 64, BB * NN / 64), 128>>>(
        x, p_Wf, p_bf, p_h1, nullptr, a_src1, a_dst1, p_s1, p_d1, CH1);
    // attention layer 1 (relu epilogue, +b1)
    attn_kernel<CH1, DD1, true><<<BB * NN, CH1>>>(p_h1, p_s1, p_d1, b1, p_att1);

    // h2 = att1 @ W2   [8192,256]@[256,128], with attn-coef epilogue (D=32)
    gemm3<CH1, false, false, false, DD2><<<dim3(CH2 / 64, BB * NN / 64), 128>>>(
        p_att1, W2, nullptr, p_h2, nullptr, a_src2, a_dst2, p_s2, p_d2, CH2);
    // attention layer 2 (+b2) -> output
    attn_kernel<CH2, DD2, false><<<BB * NN, CH2>>>(p_h2, p_s2, p_d2, b2, out);
}

// round 4
// speedup vs baseline: 1.3197x; 1.1356x over previous
#include <cuda_runtime.h>

// ---------------- problem constants ----------------
#define BB   8
#define NN   1024
#define FIN  64
#define CH1  256       // HID
#define CH2  128       // OUT
#define NH   4
#define DD1  64        // CH1/NH
#define DD2  32        // CH2/NH
#define NEG  0.2f

// ---------------- scratch (device globals; no allocation allowed) ----------------
__device__ __align__(16) float g_ne[NN * CH1];          // normalized embed
__device__ unsigned char       g_adjmask[NN * NN];      // mask bytes
__device__ int                 g_deg[NN];
__device__ int                 g_nbr[NN * NN];          // per-row neighbor lists
__device__ __align__(16) float g_Wf[FIN * CH1];         // Wp @ W1
__device__ __align__(16) float g_bf[CH1];               // bp @ W1
__device__ __align__(16) float g_h1[BB * NN * CH1];
__device__ __align__(16) float g_att1[BB * NN * CH1];
__device__ __align__(16) float g_h2[BB * NN * CH2];
__device__ float g_src1[BB * NN * NH], g_dst1[BB * NN * NH];
__device__ float g_src2[BB * NN * NH], g_dst2[BB * NN * NH];

__device__ __forceinline__ float lrelu(float x) { return x > 0.f ? x : NEG * x; }

// ---------------- 1) row-normalize embed (warp shuffles) ----------------
__global__ void norm_kernel(const float* __restrict__ embed) {
    int i = blockIdx.x, t = threadIdx.x;           // 256 threads
    float v = embed[i * CH1 + t];
    float s = v * v;
#pragma unroll
    for (int o = 16; o; o >>= 1) s += __shfl_xor_sync(0xffffffffu, s, o);
    __shared__ float ws[8];
    int w = t >> 5, lane = t & 31;
    if (lane == 0) ws[w] = s;
    __syncthreads();
    if (w == 0) {
        float x = (lane < 8) ? ws[lane] : 0.f;
#pragma unroll
        for (int o = 4; o; o >>= 1) x += __shfl_xor_sync(0xffffffffu, x, o);
        if (lane == 0) ws[0] = rsqrtf(x);
    }
    __syncthreads();
    g_ne[i * CH1 + t] = v * ws[0];
}

// ---------------- fused projection weights: Wf = Wp@W1 (row 64 = bp@W1 -> bf) ----
// 65 blocks x 256 threads; thread t = output column, fully coalesced W1 reads.
__global__ void wf_kernel(const float* __restrict__ Wp, const float* __restrict__ bp,
                          const float* __restrict__ W1,
                          float* __restrict__ Wf, float* __restrict__ bf) {
    int r = blockIdx.x;        // 0..FIN (row FIN = bias row)
    int c = threadIdx.x;       // 0..255
    const float* arow = (r < FIN) ? &Wp[r * CH1] : bp;
    float s = 0.f;
#pragma unroll 8
    for (int k = 0; k < CH1; k++)
        s = fmaf(__ldg(&arow[k]), __ldg(&W1[k * CH1 + c]), s);
    if (r < FIN) Wf[r * CH1 + c] = s;
    else         bf[c] = s;
}

// ================= unified tiled GEMM =================
// C[M,Nc] = A[M,K] @ B (+bias). BM=64, BN=64, BK=16, 128 threads, 4x8 per thread.
// TRANSB : B given row-major [Nc, K], used as B^T.
// MASKOUT: write (acc > 0.5) bytes into Cmask instead of floats.
// SYMM   : (MASKOUT only) output is symmetric; skip lower-triangle blocks and
//          mirror upper-triangle results.
// D != 0 : also emit attention coefficients gs/gd (head = col / D), D in {32,64}.
template <int K, bool TRANSB, bool BIAS, bool MASKOUT, bool SYMM, int D>
__launch_bounds__(128)
__global__ void gemm3(const float* __restrict__ A, const float* __restrict__ Bm,
                      const float* __restrict__ bias, float* __restrict__ C,
                      unsigned char* __restrict__ Cmask,
                      const float* __restrict__ asrc, const float* __restrict__ adst,
                      float* __restrict__ gs, float* __restrict__ gd, int Nc) {
    if (SYMM && blockIdx.x < blockIdx.y) return;
    constexpr int BK = 16;
    __shared__ float As[2][BK][68];   // [k][row]
    __shared__ float Bs[2][BK][68];   // [k][col]

    const int t = threadIdx.x;
    const int row0 = blockIdx.y * 64;
    const int col0 = blockIdx.x * 64;
    const int ty = t >> 3;            // 0..15 -> 4 rows each
    const int tx = t & 7;             // 0..7  -> 8 cols each

    float regA[2][4], regB[2][4];
    float acc[4][8];
#pragma unroll
    for (int i = 0; i < 4; i++)
#pragma unroll
        for (int j = 0; j < 8; j++) acc[i][j] = 0.f;

    auto loadA = [&](int k0) {
#pragma unroll
        for (int l = 0; l < 2; l++) {
            int idx = l * 128 + t;
            int r = idx >> 2, c4 = (idx & 3) * 4;
            float4 v = *(const float4*)&A[(row0 + r) * K + k0 + c4];
            regA[l][0] = v.x; regA[l][1] = v.y; regA[l][2] = v.z; regA[l][3] = v.w;
        }
    };
    auto storeA = [&](int buf) {
#pragma unroll
        for (int l = 0; l < 2; l++) {
            int idx = l * 128 + t;
            int r = idx >> 2, c4 = (idx & 3) * 4;
#pragma unroll
            for (int i = 0; i < 4; i++) As[buf][c4 + i][r] = regA[l][i];
        }
    };
    auto loadB = [&](int k0) {
#pragma unroll
        for (int l = 0; l < 2; l++) {
            int idx = l * 128 + t;
            if (TRANSB) {
                int col = idx >> 2, k4 = (idx & 3) * 4;
                float4 v = *(const float4*)&Bm[(col0 + col) * K + k0 + k4];
                regB[l][0] = v.x; regB[l][1] = v.y; regB[l][2] = v.z; regB[l][3] = v.w;
            } else {
                int row = idx >> 4, c4 = (idx & 15) * 4;
                float4 v = *(const float4*)&Bm[(k0 + row) * Nc + col0 + c4];
                regB[l][0] = v.x; regB[l][1] = v.y; regB[l][2] = v.z; regB[l][3] = v.w;
            }
        }
    };
    auto storeB = [&](int buf) {
#pragma unroll
        for (int l = 0; l < 2; l++) {
            int idx = l * 128 + t;
            if (TRANSB) {
                int col = idx >> 2, k4 = (idx & 3) * 4;
#pragma unroll
                for (int i = 0; i < 4; i++) Bs[buf][k4 + i][col] = regB[l][i];
            } else {
                int row = idx >> 4, c4 = (idx & 15) * 4;
                *(float4*)&Bs[buf][row][c4] =
                    make_float4(regB[l][0], regB[l][1], regB[l][2], regB[l][3]);
            }
        }
    };
    auto compute = [&](int buf) {
#pragma unroll
        for (int k = 0; k < BK; k++) {
            float a[4], b[8];
            *(float4*)a       = *(const float4*)&As[buf][k][ty * 4];
            *(float4*)(b)     = *(const float4*)&Bs[buf][k][tx * 8];
            *(float4*)(b + 4) = *(const float4*)&Bs[buf][k][tx * 8 + 4];
#pragma unroll
            for (int i = 0; i < 4; i++)
#pragma unroll
                for (int j = 0; j < 8; j++)
                    acc[i][j] = fmaf(a[i], b[j], acc[i][j]);
        }
    };

    loadA(0); loadB(0);
    storeA(0); storeB(0);
    __syncthreads();
    int buf = 0;
    for (int k0 = BK; k0 < K; k0 += BK) {
        loadA(k0); loadB(k0);
        compute(buf);
        storeA(buf ^ 1); storeB(buf ^ 1);
        __syncthreads();
        buf ^= 1;
    }
    compute(buf);

    if (MASKOUT) {
        const bool mirror = SYMM && (blockIdx.x != blockIdx.y);
#pragma unroll
        for (int i = 0; i < 4; i++) {
            int r = row0 + ty * 4 + i;
#pragma unroll
            for (int j = 0; j < 8; j++) {
                int c = col0 + tx * 8 + j;
                unsigned char v = (acc[i][j] > 0.5f) ? 1 : 0;
                Cmask[r * Nc + c] = v;
                if (mirror) Cmask[c * Nc + r] = v;
            }
        }
        return;
    }

    float bv[8];
    if (BIAS) {
#pragma unroll
        for (int j = 0; j < 8; j++) bv[j] = bias[col0 + tx * 8 + j];
    }
#pragma unroll
    for (int i = 0; i < 4; i++) {
#pragma unroll
        for (int j = 0; j < 8; j++) if (BIAS) acc[i][j] += bv[j];
        int r = row0 + ty * 4 + i;
        float4 v0 = make_float4(acc[i][0], acc[i][1], acc[i][2], acc[i][3]);
        float4 v1 = make_float4(acc[i][4], acc[i][5], acc[i][6], acc[i][7]);
        *(float4*)&C[r * Nc + col0 + tx * 8]     = v0;
        *(float4*)&C[r * Nc + col0 + tx * 8 + 4] = v1;
    }

    if (D) {
        const int gc0 = col0 + tx * 8;
        const int head = gc0 / D;
        float sa[8], sd[8];
#pragma unroll
        for (int j = 0; j < 8; j++) { sa[j] = asrc[gc0 + j]; sd[j] = adst[gc0 + j]; }
        float ps[4], pd[4];
#pragma unroll
        for (int i = 0; i < 4; i++) {
            float s1 = 0.f, s2 = 0.f;
#pragma unroll
            for (int j = 0; j < 8; j++) {
                s1 = fmaf(acc[i][j], sa[j], s1);
                s2 = fmaf(acc[i][j], sd[j], s2);
            }
            ps[i] = s1; pd[i] = s2;
        }
        constexpr int RED = D / 8;   // tx lanes per head
#pragma unroll
        for (int o = RED / 2; o; o >>= 1) {
#pragma unroll
            for (int i = 0; i < 4; i++) {
                ps[i] += __shfl_xor_sync(0xffffffffu, ps[i], o);
                pd[i] += __shfl_xor_sync(0xffffffffu, pd[i], o);
            }
        }
        if ((tx & (RED - 1)) == 0) {
#pragma unroll
            for (int i = 0; i < 4; i++) {
                int r = row0 + ty * 4 + i;
                gs[r * NH + head] = ps[i];
                gd[r * NH + head] = pd[i];
            }
        }
    }
}

// ---------------- 3) compact mask rows -> neighbor lists (warp ballot scan) ------
__global__ void compact_kernel() {
    int gw = (blockIdx.x * blockDim.x + threadIdx.x) >> 5;   // warp id = row
    int lane = threadIdx.x & 31;
    if (gw >= NN) return;
    const uchar4* row = (const uchar4*)&g_adjmask[gw * NN];
    int* dst = &g_nbr[gw * NN];
    int base = 0;
#pragma unroll
    for (int c = 0; c < NN / 128; c++) {
        uchar4 v = row[c * 32 + lane];
        int cnt = (int)v.x + v.y + v.z + v.w;
        int sc = cnt;
#pragma unroll
        for (int o = 1; o < 32; o <<= 1) {
            int n = __shfl_up_sync(0xffffffffu, sc, o);
            if (lane >= o) sc += n;
        }
        int pos = base + sc - cnt;
        int col = (c * 32 + lane) * 4;
        if (v.x) dst[pos++] = col;
        if (v.y) dst[pos++] = col + 1;
        if (v.z) dst[pos++] = col + 2;
        if (v.w) dst[pos++] = col + 3;
        base += __shfl_sync(0xffffffffu, sc, 31);
    }
    if (lane == 0) g_deg[gw] = base;
}

// ---------------- sparse GAT attention over neighbor lists ----------------
template <int C, int D, bool RELU>
__global__ void attn_kernel(const float* __restrict__ hin,
                            const float* __restrict__ gsrc,
                            const float* __restrict__ gdst,
                            const float* __restrict__ bias,
                            float* __restrict__ out) {
    int bn = blockIdx.x;
    int b = bn >> 10, i = bn & (NN - 1);
    int t = threadIdx.x;                        // C threads
    int hd = t / D;
    int deg = g_deg[i];
    const int* nb = &g_nbr[i * NN];

    __shared__ float sm[NH], sz[NH];
    int w = t >> 5, lane = t & 31;
    if (w < NH) {
        float adst = gdst[bn * NH + w];
        float mm = -3e38f;
        for (int k = lane; k < deg; k += 32) {
            int j = nb[k];
            float e = lrelu(adst + gsrc[(b * NN + j) * NH + w]);
            mm = fmaxf(mm, e);
        }
#pragma unroll
        for (int o = 16; o; o >>= 1) mm = fmaxf(mm, __shfl_xor_sync(0xffffffffu, mm, o));
        float zz = 0.f;
        for (int k = lane; k < deg; k += 32) {
            int j = nb[k];
            float e = lrelu(adst + gsrc[(b * NN + j) * NH + w]);
            zz += __expf(e - mm);
        }
#pragma unroll
        for (int o = 16; o; o >>= 1) zz += __shfl_xor_sync(0xffffffffu, zz, o);
        if (lane == 0) { sm[w] = mm; sz[w] = zz; }
    }
    __syncthreads();

    float adst = gdst[bn * NH + hd];
    float mh = sm[hd];
    float invZ = 1.0f / sz[hd];
    float acc = 0.f;
    for (int k = 0; k < deg; k++) {
        int j = nb[k];
        float e = lrelu(adst + gsrc[(b * NN + j) * NH + hd]);
        float wt = __expf(e - mh) * invZ;
        acc = fmaf(wt, hin[(b * NN + j) * C + t], acc);
    }
    float o = acc + bias[t];
    out[bn * C + t] = RELU ? fmaxf(o, 0.f) : o;
}

// ---------------- launcher ----------------
extern "C" void kernel_launch(void* const* d_in, const int* in_sizes, int n_in,
                              void* d_out, int out_size) {
    const float* x      = (const float*)d_in[0];
    const float* embed  = (const float*)d_in[1];
    const float* Wp     = (const float*)d_in[2];
    const float* bp     = (const float*)d_in[3];
    const float* W1     = (const float*)d_in[4];
    const float* a_src1 = (const float*)d_in[5];
    const float* a_dst1 = (const float*)d_in[6];
    const float* b1     = (const float*)d_in[7];
    const float* W2     = (const float*)d_in[8];
    const float* a_src2 = (const float*)d_in[9];
    const float* a_dst2 = (const float*)d_in[10];
    const float* b2     = (const float*)d_in[11];
    float* out = (float*)d_out;

    float *p_ne, *p_Wf, *p_bf, *p_h1, *p_att1, *p_h2, *p_s1, *p_d1, *p_s2, *p_d2;
    unsigned char* p_mask;
    cudaGetSymbolAddress((void**)&p_ne,   g_ne);
    cudaGetSymbolAddress((void**)&p_mask, g_adjmask);
    cudaGetSymbolAddress((void**)&p_Wf,   g_Wf);
    cudaGetSymbolAddress((void**)&p_bf,   g_bf);
    cudaGetSymbolAddress((void**)&p_h1,   g_h1);
    cudaGetSymbolAddress((void**)&p_att1, g_att1);
    cudaGetSymbolAddress((void**)&p_h2,   g_h2);
    cudaGetSymbolAddress((void**)&p_s1,   g_src1);
    cudaGetSymbolAddress((void**)&p_d1,   g_dst1);
    cudaGetSymbolAddress((void**)&p_s2,   g_src2);
    cudaGetSymbolAddress((void**)&p_d2,   g_dst2);

    // adjacency pipeline (batch-independent)
    norm_kernel<<<NN, CH1>>>(embed);
    // mask = (ne @ ne^T) > 0.5 — symmetric, upper-triangle blocks only
    gemm3<CH1, true, false, true, true, 0><<<dim3(NN / 64, NN / 64), 128>>>(
        p_ne, p_ne, nullptr, nullptr, p_mask, nullptr, nullptr, nullptr, nullptr, NN);
    compact_kernel<<<NN / 8, 256>>>();

    // fused projection: Wf = Wp @ W1 (+ bf = bp @ W1 as row 64)
    wf_kernel<<<FIN + 1, CH1>>>(Wp, bp, W1, p_Wf, p_bf);

    // h1 = x @ Wf + bf   [8192,64]@[64,256], with attn-coef epilogue (D=64)
    gemm3<FIN, false, true, false, false, DD1><<<dim3(CH1 / 64, BB * NN / 64), 128>>>(
        x, p_Wf, p_bf, p_h1, nullptr, a_src1, a_dst1, p_s1, p_d1, CH1);
    // attention layer 1 (relu epilogue, +b1)
    attn_kernel<CH1, DD1, true><<<BB * NN, CH1>>>(p_h1, p_s1, p_d1, b1, p_att1);

    // h2 = att1 @ W2   [8192,256]@[256,128], with attn-coef epilogue (D=32)
    gemm3<CH1, false, false, false, false, DD2><<<dim3(CH2 / 64, BB * NN / 64), 128>>>(
        p_att1, W2, nullptr, p_h2, nullptr, a_src2, a_dst2, p_s2, p_d2, CH2);
    // attention layer 2 (+b2) -> output
    attn_kernel<CH2, DD2, false><<<BB * NN, CH2>>>(p_h2, p_s2, p_d2, b2, out);
}

// round 5
// speedup vs baseline: 1.3656x; 1.0348x over previous
#include <cuda_runtime.h>

// ---------------- problem constants ----------------
#define BB   8
#define NN   1024
#define FIN  64
#define CH1  256       // HID
#define CH2  128       // OUT
#define NH   4
#define DD1  64        // CH1/NH
#define DD2  32        // CH2/NH
#define NEG  0.2f

// ---------------- scratch (device globals; no allocation allowed) ----------------
__device__ __align__(16) float g_ne[NN * CH1];          // normalized embed
__device__ unsigned char       g_adjmask[NN * NN];      // mask bytes
__device__ int                 g_deg[NN];
__device__ int                 g_nbr[NN * NN];          // per-row neighbor lists
__device__ __align__(16) float g_Wf[FIN * CH1];         // Wp @ W1
__device__ __align__(16) float g_bf[CH1];               // bp @ W1
__device__ __align__(16) float g_h1[BB * NN * CH1];
__device__ __align__(16) float g_att1[BB * NN * CH1];
__device__ __align__(16) float g_h2[BB * NN * CH2];
__device__ float g_src1[BB * NN * NH], g_dst1[BB * NN * NH];
__device__ float g_src2[BB * NN * NH], g_dst2[BB * NN * NH];

__device__ __forceinline__ float lrelu(float x) { return x > 0.f ? x : NEG * x; }

// ---------------- 1) row-normalize embed (warp shuffles) ----------------
__global__ void norm_kernel(const float* __restrict__ embed) {
    int i = blockIdx.x, t = threadIdx.x;           // 256 threads
    float v = embed[i * CH1 + t];
    float s = v * v;
#pragma unroll
    for (int o = 16; o; o >>= 1) s += __shfl_xor_sync(0xffffffffu, s, o);
    __shared__ float ws[8];
    int w = t >> 5, lane = t & 31;
    if (lane == 0) ws[w] = s;
    __syncthreads();
    if (w == 0) {
        float x = (lane < 8) ? ws[lane] : 0.f;
#pragma unroll
        for (int o = 4; o; o >>= 1) x += __shfl_xor_sync(0xffffffffu, x, o);
        if (lane == 0) ws[0] = rsqrtf(x);
    }
    __syncthreads();
    g_ne[i * CH1 + t] = v * ws[0];
}

// ---------------- fused projection weights: Wf = Wp@W1, bf = bp@W1 ----------------
// split-K: grid (65, 4), 256 threads. Block (r, cb) computes 64 output columns
// of row r (row FIN = bias row). Thread = (k-slice of 64) x (1 column).
__global__ void wf_kernel(const float* __restrict__ Wp, const float* __restrict__ bp,
                          const float* __restrict__ W1,
                          float* __restrict__ Wf, float* __restrict__ bf) {
    int r  = blockIdx.x;              // 0..FIN
    int c0 = blockIdx.y * 64;
    int t  = threadIdx.x;
    int col = t & 63, ks = t >> 6;    // 4 k-slices of 64
    const float* arow = (r < FIN) ? &Wp[r * CH1] : bp;
    float s = 0.f;
    int kbase = ks * 64;
#pragma unroll 8
    for (int k = 0; k < 64; k++)
        s = fmaf(__ldg(&arow[kbase + k]), __ldg(&W1[(kbase + k) * CH1 + c0 + col]), s);
    __shared__ float red[256];
    red[t] = s;
    __syncthreads();
    if (t < 128) red[t] += red[t + 128];
    __syncthreads();
    if (t < 64) {
        float v = red[t] + red[t + 64];
        if (r < FIN) Wf[r * CH1 + c0 + t] = v;
        else         bf[c0 + t] = v;
    }
}

// ================= unified tiled GEMM =================
// C[M,Nc] = A[M,K] @ B (+bias). BM=64, BN=64, BK=16, 128 threads, 4x8 per thread.
// TRANSB : B given row-major [Nc, K], used as B^T.
// MASKOUT: write (acc > 0.5) bytes into Cmask instead of floats.
// SYMM   : (MASKOUT only) skip lower-triangle blocks, mirror upper-triangle.
// D != 0 : also emit attention coefficients gs/gd (head = col / D), D in {32,64}.
template <int K, bool TRANSB, bool BIAS, bool MASKOUT, bool SYMM, int D>
__launch_bounds__(128)
__global__ void gemm3(const float* __restrict__ A, const float* __restrict__ Bm,
                      const float* __restrict__ bias, float* __restrict__ C,
                      unsigned char* __restrict__ Cmask,
                      const float* __restrict__ asrc, const float* __restrict__ adst,
                      float* __restrict__ gs, float* __restrict__ gd, int Nc) {
    if (SYMM && blockIdx.x < blockIdx.y) return;
    constexpr int BK = 16;
    __shared__ float As[2][BK][68];   // [k][row]
    __shared__ float Bs[2][BK][68];   // [k][col]

    const int t = threadIdx.x;
    const int row0 = blockIdx.y * 64;
    const int col0 = blockIdx.x * 64;
    const int ty = t >> 3;            // 0..15 -> 4 rows each
    const int tx = t & 7;             // 0..7  -> 8 cols each

    float regA[2][4], regB[2][4];
    float acc[4][8];
#pragma unroll
    for (int i = 0; i < 4; i++)
#pragma unroll
        for (int j = 0; j < 8; j++) acc[i][j] = 0.f;

    auto loadA = [&](int k0) {
#pragma unroll
        for (int l = 0; l < 2; l++) {
            int idx = l * 128 + t;
            int r = idx >> 2, c4 = (idx & 3) * 4;
            float4 v = *(const float4*)&A[(row0 + r) * K + k0 + c4];
            regA[l][0] = v.x; regA[l][1] = v.y; regA[l][2] = v.z; regA[l][3] = v.w;
        }
    };
    auto storeA = [&](int buf) {
#pragma unroll
        for (int l = 0; l < 2; l++) {
            int idx = l * 128 + t;
            int r = idx >> 2, c4 = (idx & 3) * 4;
#pragma unroll
            for (int i = 0; i < 4; i++) As[buf][c4 + i][r] = regA[l][i];
        }
    };
    auto loadB = [&](int k0) {
#pragma unroll
        for (int l = 0; l < 2; l++) {
            int idx = l * 128 + t;
            if (TRANSB) {
                int col = idx >> 2, k4 = (idx & 3) * 4;
                float4 v = *(const float4*)&Bm[(col0 + col) * K + k0 + k4];
                regB[l][0] = v.x; regB[l][1] = v.y; regB[l][2] = v.z; regB[l][3] = v.w;
            } else {
                int row = idx >> 4, c4 = (idx & 15) * 4;
                float4 v = *(const float4*)&Bm[(k0 + row) * Nc + col0 + c4];
                regB[l][0] = v.x; regB[l][1] = v.y; regB[l][2] = v.z; regB[l][3] = v.w;
            }
        }
    };
    auto storeB = [&](int buf) {
#pragma unroll
        for (int l = 0; l < 2; l++) {
            int idx = l * 128 + t;
            if (TRANSB) {
                int col = idx >> 2, k4 = (idx & 3) * 4;
#pragma unroll
                for (int i = 0; i < 4; i++) Bs[buf][k4 + i][col] = regB[l][i];
            } else {
                int row = idx >> 4, c4 = (idx & 15) * 4;
                *(float4*)&Bs[buf][row][c4] =
                    make_float4(regB[l][0], regB[l][1], regB[l][2], regB[l][3]);
            }
        }
    };
    auto compute = [&](int buf) {
#pragma unroll
        for (int k = 0; k < BK; k++) {
            float a[4], b[8];
            *(float4*)a       = *(const float4*)&As[buf][k][ty * 4];
            *(float4*)(b)     = *(const float4*)&Bs[buf][k][tx * 8];
            *(float4*)(b + 4) = *(const float4*)&Bs[buf][k][tx * 8 + 4];
#pragma unroll
            for (int i = 0; i < 4; i++)
#pragma unroll
                for (int j = 0; j < 8; j++)
                    acc[i][j] = fmaf(a[i], b[j], acc[i][j]);
        }
    };

    loadA(0); loadB(0);
    storeA(0); storeB(0);
    __syncthreads();
    int buf = 0;
    for (int k0 = BK; k0 < K; k0 += BK) {
        loadA(k0); loadB(k0);
        compute(buf);
        storeA(buf ^ 1); storeB(buf ^ 1);
        __syncthreads();
        buf ^= 1;
    }
    compute(buf);

    if (MASKOUT) {
        const bool mirror = SYMM && (blockIdx.x != blockIdx.y);
#pragma unroll
        for (int i = 0; i < 4; i++) {
            int r = row0 + ty * 4 + i;
#pragma unroll
            for (int j = 0; j < 8; j++) {
                int c = col0 + tx * 8 + j;
                unsigned char v = (acc[i][j] > 0.5f) ? 1 : 0;
                Cmask[r * Nc + c] = v;
                if (mirror) Cmask[c * Nc + r] = v;
            }
        }
        return;
    }

    float bv[8];
    if (BIAS) {
#pragma unroll
        for (int j = 0; j < 8; j++) bv[j] = bias[col0 + tx * 8 + j];
    }
#pragma unroll
    for (int i = 0; i < 4; i++) {
#pragma unroll
        for (int j = 0; j < 8; j++) if (BIAS) acc[i][j] += bv[j];
        int r = row0 + ty * 4 + i;
        float4 v0 = make_float4(acc[i][0], acc[i][1], acc[i][2], acc[i][3]);
        float4 v1 = make_float4(acc[i][4], acc[i][5], acc[i][6], acc[i][7]);
        *(float4*)&C[r * Nc + col0 + tx * 8]     = v0;
        *(float4*)&C[r * Nc + col0 + tx * 8 + 4] = v1;
    }

    if (D) {
        const int gc0 = col0 + tx * 8;
        const int head = gc0 / D;
        float sa[8], sd[8];
#pragma unroll
        for (int j = 0; j < 8; j++) { sa[j] = asrc[gc0 + j]; sd[j] = adst[gc0 + j]; }
        float ps[4], pd[4];
#pragma unroll
        for (int i = 0; i < 4; i++) {
            float s1 = 0.f, s2 = 0.f;
#pragma unroll
            for (int j = 0; j < 8; j++) {
                s1 = fmaf(acc[i][j], sa[j], s1);
                s2 = fmaf(acc[i][j], sd[j], s2);
            }
            ps[i] = s1; pd[i] = s2;
        }
        constexpr int RED = D / 8;   // tx lanes per head
#pragma unroll
        for (int o = RED / 2; o; o >>= 1) {
#pragma unroll
            for (int i = 0; i < 4; i++) {
                ps[i] += __shfl_xor_sync(0xffffffffu, ps[i], o);
                pd[i] += __shfl_xor_sync(0xffffffffu, pd[i], o);
            }
        }
        if ((tx & (RED - 1)) == 0) {
#pragma unroll
            for (int i = 0; i < 4; i++) {
                int r = row0 + ty * 4 + i;
                gs[r * NH + head] = ps[i];
                gd[r * NH + head] = pd[i];
            }
        }
    }
}

// ---------------- 3) compact mask rows -> neighbor lists (warp ballot scan) ------
__global__ void compact_kernel() {
    int gw = (blockIdx.x * blockDim.x + threadIdx.x) >> 5;   // warp id = row
    int lane = threadIdx.x & 31;
    if (gw >= NN) return;
    const uchar4* row = (const uchar4*)&g_adjmask[gw * NN];
    int* dst = &g_nbr[gw * NN];
    int base = 0;
#pragma unroll
    for (int c = 0; c < NN / 128; c++) {
        uchar4 v = row[c * 32 + lane];
        int cnt = (int)v.x + v.y + v.z + v.w;
        int sc = cnt;
#pragma unroll
        for (int o = 1; o < 32; o <<= 1) {
            int n = __shfl_up_sync(0xffffffffu, sc, o);
            if (lane >= o) sc += n;
        }
        int pos = base + sc - cnt;
        int col = (c * 32 + lane) * 4;
        if (v.x) dst[pos++] = col;
        if (v.y) dst[pos++] = col + 1;
        if (v.z) dst[pos++] = col + 2;
        if (v.w) dst[pos++] = col + 3;
        base += __shfl_sync(0xffffffffu, sc, 31);
    }
    if (lane == 0) g_deg[gw] = base;
}

// ---------------- sparse GAT attention over neighbor lists ----------------
template <int C, int D, bool RELU>
__global__ void attn_kernel(const float* __restrict__ hin,
                            const float* __restrict__ gsrc,
                            const float* __restrict__ gdst,
                            const float* __restrict__ bias,
                            float* __restrict__ out) {
    int bn = blockIdx.x;
    int b = bn >> 10, i = bn & (NN - 1);
    int t = threadIdx.x;                        // C threads
    int hd = t / D;
    int deg = g_deg[i];
    const int* nb = &g_nbr[i * NN];

    __shared__ float sm[NH], sz[NH];
    int w = t >> 5, lane = t & 31;
    if (w < NH) {
        float adst = gdst[bn * NH + w];
        float mm = -3e38f;
        for (int k = lane; k < deg; k += 32) {
            int j = nb[k];
            float e = lrelu(adst + gsrc[(b * NN + j) * NH + w]);
            mm = fmaxf(mm, e);
        }
#pragma unroll
        for (int o = 16; o; o >>= 1) mm = fmaxf(mm, __shfl_xor_sync(0xffffffffu, mm, o));
        float zz = 0.f;
        for (int k = lane; k < deg; k += 32) {
            int j = nb[k];
            float e = lrelu(adst + gsrc[(b * NN + j) * NH + w]);
            zz += __expf(e - mm);
        }
#pragma unroll
        for (int o = 16; o; o >>= 1) zz += __shfl_xor_sync(0xffffffffu, zz, o);
        if (lane == 0) { sm[w] = mm; sz[w] = zz; }
    }
    __syncthreads();

    float adst = gdst[bn * NH + hd];
    float mh = sm[hd];
    float invZ = 1.0f / sz[hd];
    float acc = 0.f;
    for (int k = 0; k < deg; k++) {
        int j = nb[k];
        float e = lrelu(adst + gsrc[(b * NN + j) * NH + hd]);
        float wt = __expf(e - mh) * invZ;
        acc = fmaf(wt, hin[(b * NN + j) * C + t], acc);
    }
    float o = acc + bias[t];
    out[bn * C + t] = RELU ? fmaxf(o, 0.f) : o;
}

// ---------------- launcher ----------------
extern "C" void kernel_launch(void* const* d_in, const int* in_sizes, int n_in,
                              void* d_out, int out_size) {
    const float* x      = (const float*)d_in[0];
    const float* embed  = (const float*)d_in[1];
    const float* Wp     = (const float*)d_in[2];
    const float* bp     = (const float*)d_in[3];
    const float* W1     = (const float*)d_in[4];
    const float* a_src1 = (const float*)d_in[5];
    const float* a_dst1 = (const float*)d_in[6];
    const float* b1     = (const float*)d_in[7];
    const float* W2     = (const float*)d_in[8];
    const float* a_src2 = (const float*)d_in[9];
    const float* a_dst2 = (const float*)d_in[10];
    const float* b2     = (const float*)d_in[11];
    float* out = (float*)d_out;

    float *p_ne, *p_Wf, *p_bf, *p_h1, *p_att1, *p_h2, *p_s1, *p_d1, *p_s2, *p_d2;
    unsigned char* p_mask;
    cudaGetSymbolAddress((void**)&p_ne,   g_ne);
    cudaGetSymbolAddress((void**)&p_mask, g_adjmask);
    cudaGetSymbolAddress((void**)&p_Wf,   g_Wf);
    cudaGetSymbolAddress((void**)&p_bf,   g_bf);
    cudaGetSymbolAddress((void**)&p_h1,   g_h1);
    cudaGetSymbolAddress((void**)&p_att1, g_att1);
    cudaGetSymbolAddress((void**)&p_h2,   g_h2);
    cudaGetSymbolAddress((void**)&p_s1,   g_src1);
    cudaGetSymbolAddress((void**)&p_d1,   g_dst1);
    cudaGetSymbolAddress((void**)&p_s2,   g_src2);
    cudaGetSymbolAddress((void**)&p_d2,   g_dst2);

    // adjacency pipeline (batch-independent)
    norm_kernel<<<NN, CH1>>>(embed);
    // mask = (ne @ ne^T) > 0.5 — symmetric, upper-triangle blocks only
    gemm3<CH1, true, false, true, true, 0><<<dim3(NN / 64, NN / 64), 128>>>(
        p_ne, p_ne, nullptr, nullptr, p_mask, nullptr, nullptr, nullptr, nullptr, NN);
    compact_kernel<<<NN / 8, 256>>>();

    // fused projection: Wf = Wp @ W1 (+ bf = bp @ W1 as row 64) — split-K
    wf_kernel<<<dim3(FIN + 1, 4), 256>>>(Wp, bp, W1, p_Wf, p_bf);

    // h1 = x @ Wf + bf   [8192,64]@[64,256], with attn-coef epilogue (D=64)
    gemm3<FIN, false, true, false, false, DD1><<<dim3(CH1 / 64, BB * NN / 64), 128>>>(
        x, p_Wf, p_bf, p_h1, nullptr, a_src1, a_dst1, p_s1, p_d1, CH1);
    // attention layer 1 (relu epilogue, +b1)
    attn_kernel<CH1, DD1, true><<<BB * NN, CH1>>>(p_h1, p_s1, p_d1, b1, p_att1);

    // h2 = att1 @ W2   [8192,256]@[256,128], with attn-coef epilogue (D=32)
    gemm3<CH1, false, false, false, false, DD2><<<dim3(CH2 / 64, BB * NN / 64), 128>>>(
        p_att1, W2, nullptr, p_h2, nullptr, a_src2, a_dst2, p_s2, p_d2, CH2);
    // attention layer 2 (+b2) -> output
    attn_kernel<CH2, DD2, false><<<BB * NN, CH2>>>(p_h2, p_s2, p_d2, b2, out);
}

// round 7
// speedup vs baseline: 1.3660x; 1.0003x over previous
#include <cuda_runtime.h>

// ---------------- problem constants ----------------
#define BB   8
#define NN   1024
#define FIN  64
#define CH1  256       // HID
#define CH2  128       // OUT
#define NH   4
#define DD1  64        // CH1/NH
#define DD2  32        // CH2/NH
#define NEG  0.2f

// ---------------- scratch (device globals; no allocation allowed) ----------------
__device__ __align__(16) float g_ne[NN * CH1];          // normalized embed
__device__ unsigned char       g_adjmask[NN * NN];      // mask bytes
__device__ int                 g_deg[NN];
__device__ int                 g_nbr[NN * NN];          // per-row neighbor lists
__device__ __align__(16) float g_Wf[FIN * CH1];         // Wp @ W1
__device__ __align__(16) float g_bf[CH1];               // bp @ W1
__device__ __align__(16) float g_h1[BB * NN * CH1];
__device__ __align__(16) float g_att1[BB * NN * CH1];
__device__ __align__(16) float g_h2[BB * NN * CH2];
__device__ float g_src1[BB * NN * NH], g_dst1[BB * NN * NH];
__device__ float g_src2[BB * NN * NH], g_dst2[BB * NN * NH];

__device__ __forceinline__ float lrelu(float x) { return x > 0.f ? x : NEG * x; }

// ---------------- 1) row-normalize embed (warp shuffles) ----------------
__global__ void norm_kernel(const float* __restrict__ embed) {
    int i = blockIdx.x, t = threadIdx.x;           // 256 threads
    float v = embed[i * CH1 + t];
    float s = v * v;
#pragma unroll
    for (int o = 16; o; o >>= 1) s += __shfl_xor_sync(0xffffffffu, s, o);
    __shared__ float ws[8];
    int w = t >> 5, lane = t & 31;
    if (lane == 0) ws[w] = s;
    __syncthreads();
    if (w == 0) {
        float x = (lane < 8) ? ws[lane] : 0.f;
#pragma unroll
        for (int o = 4; o; o >>= 1) x += __shfl_xor_sync(0xffffffffu, x, o);
        if (lane == 0) ws[0] = rsqrtf(x);
    }
    __syncthreads();
    g_ne[i * CH1 + t] = v * ws[0];
}

// ---------------- fused projection weights: Wf = Wp@W1, bf = bp@W1 ----------------
// split-K x16: grid (65, 4), 1024 threads. Block (r, cb) computes 64 output
// columns of row r (row FIN = bias row). Thread = (k-slice of 16) x (1 column).
__global__ __launch_bounds__(1024)
void wf_kernel(const float* __restrict__ Wp, const float* __restrict__ bp,
               const float* __restrict__ W1,
               float* __restrict__ Wf, float* __restrict__ bf) {
    int r  = blockIdx.x;              // 0..FIN
    int c0 = blockIdx.y * 64;
    int t  = threadIdx.x;
    int col = t & 63, ks = t >> 6;    // 16 k-slices of 16
    const float* arow = (r < FIN) ? &Wp[r * CH1] : bp;
    float s = 0.f;
    int kbase = ks * 16;
#pragma unroll
    for (int k = 0; k < 16; k++)
        s = fmaf(__ldg(&arow[kbase + k]), __ldg(&W1[(kbase + k) * CH1 + c0 + col]), s);
    __shared__ float red[1024];
    red[t] = s;
    __syncthreads();
#pragma unroll
    for (int off = 512; off >= 64; off >>= 1) {
        if (t < off) red[t] += red[t + off];
        __syncthreads();
    }
    if (t < 64) {
        float v = red[t];
        if (r < FIN) Wf[r * CH1 + c0 + t] = v;
        else         bf[c0 + t] = v;
    }
}

// ================= unified tiled GEMM =================
// C[M,Nc] = A[M,K] @ B (+bias). BM=64, BN=64, BK=16, 128 threads, 4x8 per thread.
// TRANSB : B given row-major [Nc, K], used as B^T.
// MASKOUT: write (acc > 0.5) bytes into Cmask instead of floats.
// SYMM   : (MASKOUT only) skip lower-triangle blocks, mirror upper-triangle.
// D != 0 : also emit attention coefficients gs/gd (head = col / D), D in {32,64}.
template <int K, bool TRANSB, bool BIAS, bool MASKOUT, bool SYMM, int D>
__launch_bounds__(128)
__global__ void gemm3(const float* __restrict__ A, const float* __restrict__ Bm,
                      const float* __restrict__ bias, float* __restrict__ C,
                      unsigned char* __restrict__ Cmask,
                      const float* __restrict__ asrc, const float* __restrict__ adst,
                      float* __restrict__ gs, float* __restrict__ gd, int Nc) {
    if (SYMM && blockIdx.x < blockIdx.y) return;
    constexpr int BK = 16;
    __shared__ float As[2][BK][68];   // [k][row]
    __shared__ float Bs[2][BK][68];   // [k][col]

    const int t = threadIdx.x;
    const int row0 = blockIdx.y * 64;
    const int col0 = blockIdx.x * 64;
    const int ty = t >> 3;            // 0..15 -> 4 rows each
    const int tx = t & 7;             // 0..7  -> 8 cols each

    float regA[2][4], regB[2][4];
    float acc[4][8];
#pragma unroll
    for (int i = 0; i < 4; i++)
#pragma unroll
        for (int j = 0; j < 8; j++) acc[i][j] = 0.f;

    auto loadA = [&](int k0) {
#pragma unroll
        for (int l = 0; l < 2; l++) {
            int idx = l * 128 + t;
            int r = idx >> 2, c4 = (idx & 3) * 4;
            float4 v = *(const float4*)&A[(row0 + r) * K + k0 + c4];
            regA[l][0] = v.x; regA[l][1] = v.y; regA[l][2] = v.z; regA[l][3] = v.w;
        }
    };
    auto storeA = [&](int buf) {
#pragma unroll
        for (int l = 0; l < 2; l++) {
            int idx = l * 128 + t;
            int r = idx >> 2, c4 = (idx & 3) * 4;
#pragma unroll
            for (int i = 0; i < 4; i++) As[buf][c4 + i][r] = regA[l][i];
        }
    };
    auto loadB = [&](int k0) {
#pragma unroll
        for (int l = 0; l < 2; l++) {
            int idx = l * 128 + t;
            if (TRANSB) {
                int col = idx >> 2, k4 = (idx & 3) * 4;
                float4 v = *(const float4*)&Bm[(col0 + col) * K + k0 + k4];
                regB[l][0] = v.x; regB[l][1] = v.y; regB[l][2] = v.z; regB[l][3] = v.w;
            } else {
                int row = idx >> 4, c4 = (idx & 15) * 4;
                float4 v = *(const float4*)&Bm[(k0 + row) * Nc + col0 + c4];
                regB[l][0] = v.x; regB[l][1] = v.y; regB[l][2] = v.z; regB[l][3] = v.w;
            }
        }
    };
    auto storeB = [&](int buf) {
#pragma unroll
        for (int l = 0; l < 2; l++) {
            int idx = l * 128 + t;
            if (TRANSB) {
                int col = idx >> 2, k4 = (idx & 3) * 4;
#pragma unroll
                for (int i = 0; i < 4; i++) Bs[buf][k4 + i][col] = regB[l][i];
            } else {
                int row = idx >> 4, c4 = (idx & 15) * 4;
                *(float4*)&Bs[buf][row][c4] =
                    make_float4(regB[l][0], regB[l][1], regB[l][2], regB[l][3]);
            }
        }
    };
    auto compute = [&](int buf) {
#pragma unroll
        for (int k = 0; k < BK; k++) {
            float a[4], b[8];
            *(float4*)a       = *(const float4*)&As[buf][k][ty * 4];
            *(float4*)(b)     = *(const float4*)&Bs[buf][k][tx * 8];
            *(float4*)(b + 4) = *(const float4*)&Bs[buf][k][tx * 8 + 4];
#pragma unroll
            for (int i = 0; i < 4; i++)
#pragma unroll
                for (int j = 0; j < 8; j++)
                    acc[i][j] = fmaf(a[i], b[j], acc[i][j]);
        }
    };

    loadA(0); loadB(0);
    storeA(0); storeB(0);
    __syncthreads();
    int buf = 0;
    for (int k0 = BK; k0 < K; k0 += BK) {
        loadA(k0); loadB(k0);
        compute(buf);
        storeA(buf ^ 1); storeB(buf ^ 1);
        __syncthreads();
        buf ^= 1;
    }
    compute(buf);

    if (MASKOUT) {
        const bool mirror = SYMM && (blockIdx.x != blockIdx.y);
#pragma unroll
        for (int i = 0; i < 4; i++) {
            int r = row0 + ty * 4 + i;
#pragma unroll
            for (int j = 0; j < 8; j++) {
                int c = col0 + tx * 8 + j;
                unsigned char v = (acc[i][j] > 0.5f) ? 1 : 0;
                Cmask[r * Nc + c] = v;
                if (mirror) Cmask[c * Nc + r] = v;
            }
        }
        return;
    }

    float bv[8];
    if (BIAS) {
#pragma unroll
        for (int j = 0; j < 8; j++) bv[j] = bias[col0 + tx * 8 + j];
    }
#pragma unroll
    for (int i = 0; i < 4; i++) {
#pragma unroll
        for (int j = 0; j < 8; j++) if (BIAS) acc[i][j] += bv[j];
        int r = row0 + ty * 4 + i;
        float4 v0 = make_float4(acc[i][0], acc[i][1], acc[i][2], acc[i][3]);
        float4 v1 = make_float4(acc[i][4], acc[i][5], acc[i][6], acc[i][7]);
        *(float4*)&C[r * Nc + col0 + tx * 8]     = v0;
        *(float4*)&C[r * Nc + col0 + tx * 8 + 4] = v1;
    }

    if (D) {
        const int gc0 = col0 + tx * 8;
        const int head = gc0 / D;
        float sa[8], sd[8];
#pragma unroll
        for (int j = 0; j < 8; j++) { sa[j] = asrc[gc0 + j]; sd[j] = adst[gc0 + j]; }
        float ps[4], pd[4];
#pragma unroll
        for (int i = 0; i < 4; i++) {
            float s1 = 0.f, s2 = 0.f;
#pragma unroll
            for (int j = 0; j < 8; j++) {
                s1 = fmaf(acc[i][j], sa[j], s1);
                s2 = fmaf(acc[i][j], sd[j], s2);
            }
            ps[i] = s1; pd[i] = s2;
        }
        constexpr int RED = D / 8;   // tx lanes per head
#pragma unroll
        for (int o = RED / 2; o; o >>= 1) {
#pragma unroll
            for (int i = 0; i < 4; i++) {
                ps[i] += __shfl_xor_sync(0xffffffffu, ps[i], o);
                pd[i] += __shfl_xor_sync(0xffffffffu, pd[i], o);
            }
        }
        if ((tx & (RED - 1)) == 0) {
#pragma unroll
            for (int i = 0; i < 4; i++) {
                int r = row0 + ty * 4 + i;
                gs[r * NH + head] = ps[i];
                gd[r * NH + head] = pd[i];
            }
        }
    }
}

// ---------------- 3) compact mask rows -> neighbor lists (warp ballot scan) ------
__global__ void compact_kernel() {
    int gw = (blockIdx.x * blockDim.x + threadIdx.x) >> 5;   // warp id = row
    int lane = threadIdx.x & 31;
    if (gw >= NN) return;
    const uchar4* row = (const uchar4*)&g_adjmask[gw * NN];
    int* dst = &g_nbr[gw * NN];
    int base = 0;
#pragma unroll
    for (int c = 0; c < NN / 128; c++) {
        uchar4 v = row[c * 32 + lane];
        int cnt = (int)v.x + v.y + v.z + v.w;
        int sc = cnt;
#pragma unroll
        for (int o = 1; o < 32; o <<= 1) {
            int n = __shfl_up_sync(0xffffffffu, sc, o);
            if (lane >= o) sc += n;
        }
        int pos = base + sc - cnt;
        int col = (c * 32 + lane) * 4;
        if (v.x) dst[pos++] = col;
        if (v.y) dst[pos++] = col + 1;
        if (v.z) dst[pos++] = col + 2;
        if (v.w) dst[pos++] = col + 3;
        base += __shfl_sync(0xffffffffu, sc, 31);
    }
    if (lane == 0) g_deg[gw] = base;
}

// ---------------- sparse GAT attention over neighbor lists ----------------
template <int C, int D, bool RELU>
__global__ void attn_kernel(const float* __restrict__ hin,
                            const float* __restrict__ gsrc,
                            const float* __restrict__ gdst,
                            const float* __restrict__ bias,
                            float* __restrict__ out) {
    int bn = blockIdx.x;
    int b = bn >> 10, i = bn & (NN - 1);
    int t = threadIdx.x;                        // C threads
    int hd = t / D;
    int deg = g_deg[i];
    const int* nb = &g_nbr[i * NN];

    __shared__ float sm[NH], sz[NH];
    int w = t >> 5, lane = t & 31;
    if (w < NH) {
        float adst = gdst[bn * NH + w];
        float mm = -3e38f;
        for (int k = lane; k < deg; k += 32) {
            int j = nb[k];
            float e = lrelu(adst + gsrc[(b * NN + j) * NH + w]);
            mm = fmaxf(mm, e);
        }
#pragma unroll
        for (int o = 16; o; o >>= 1) mm = fmaxf(mm, __shfl_xor_sync(0xffffffffu, mm, o));
        float zz = 0.f;
        for (int k = lane; k < deg; k += 32) {
            int j = nb[k];
            float e = lrelu(adst + gsrc[(b * NN + j) * NH + w]);
            zz += __expf(e - mm);
        }
#pragma unroll
        for (int o = 16; o; o >>= 1) zz += __shfl_xor_sync(0xffffffffu, zz, o);
        if (lane == 0) { sm[w] = mm; sz[w] = zz; }
    }
    __syncthreads();

    float adst = gdst[bn * NH + hd];
    float mh = sm[hd];
    float invZ = 1.0f / sz[hd];
    float acc = 0.f;
    for (int k = 0; k < deg; k++) {
        int j = nb[k];
        float e = lrelu(adst + gsrc[(b * NN + j) * NH + hd]);
        float wt = __expf(e - mh) * invZ;
        acc = fmaf(wt, hin[(b * NN + j) * C + t], acc);
    }
    float o = acc + bias[t];
    out[bn * C + t] = RELU ? fmaxf(o, 0.f) : o;
}

// ---------------- launcher ----------------
extern "C" void kernel_launch(void* const* d_in, const int* in_sizes, int n_in,
                              void* d_out, int out_size) {
    const float* x      = (const float*)d_in[0];
    const float* embed  = (const float*)d_in[1];
    const float* Wp     = (const float*)d_in[2];
    const float* bp     = (const float*)d_in[3];
    const float* W1     = (const float*)d_in[4];
    const float* a_src1 = (const float*)d_in[5];
    const float* a_dst1 = (const float*)d_in[6];
    const float* b1     = (const float*)d_in[7];
    const float* W2     = (const float*)d_in[8];
    const float* a_src2 = (const float*)d_in[9];
    const float* a_dst2 = (const float*)d_in[10];
    const float* b2     = (const float*)d_in[11];
    float* out = (float*)d_out;

    float *p_ne, *p_Wf, *p_bf, *p_h1, *p_att1, *p_h2, *p_s1, *p_d1, *p_s2, *p_d2;
    unsigned char* p_mask;
    cudaGetSymbolAddress((void**)&p_ne,   g_ne);
    cudaGetSymbolAddress((void**)&p_mask, g_adjmask);
    cudaGetSymbolAddress((void**)&p_Wf,   g_Wf);
    cudaGetSymbolAddress((void**)&p_bf,   g_bf);
    cudaGetSymbolAddress((void**)&p_h1,   g_h1);
    cudaGetSymbolAddress((void**)&p_att1, g_att1);
    cudaGetSymbolAddress((void**)&p_h2,   g_h2);
    cudaGetSymbolAddress((void**)&p_s1,   g_src1);
    cudaGetSymbolAddress((void**)&p_d1,   g_dst1);
    cudaGetSymbolAddress((void**)&p_s2,   g_src2);
    cudaGetSymbolAddress((void**)&p_d2,   g_dst2);

    // adjacency pipeline (batch-independent)
    norm_kernel<<<NN, CH1>>>(embed);
    // mask = (ne @ ne^T) > 0.5 — symmetric, upper-triangle blocks only
    gemm3<CH1, true, false, true, true, 0><<<dim3(NN / 64, NN / 64), 128>>>(
        p_ne, p_ne, nullptr, nullptr, p_mask, nullptr, nullptr, nullptr, nullptr, NN);
    compact_kernel<<<NN / 8, 256>>>();

    // fused projection: Wf = Wp @ W1 (+ bf = bp @ W1 as row 64) — split-K x16
    wf_kernel<<<dim3(FIN + 1, 4), 1024>>>(Wp, bp, W1, p_Wf, p_bf);

    // h1 = x @ Wf + bf   [8192,64]@[64,256], with attn-coef epilogue (D=64)
    gemm3<FIN, false, true, false, false, DD1><<<dim3(CH1 / 64, BB * NN / 64), 128>>>(
        x, p_Wf, p_bf, p_h1, nullptr, a_src1, a_dst1, p_s1, p_d1, CH1);
    // attention layer 1 (relu epilogue, +b1)
    attn_kernel<CH1, DD1, true><<<BB * NN, CH1>>>(p_h1, p_s1, p_d1, b1, p_att1);

    // h2 = att1 @ W2   [8192,256]@[256,128], with attn-coef epilogue (D=32)
    gemm3<CH1, false, false, false, false, DD2><<<dim3(CH2 / 64, BB * NN / 64), 128>>>(
        p_att1, W2, nullptr, p_h2, nullptr, a_src2, a_dst2, p_s2, p_d2, CH2);
    // attention layer 2 (+b2) -> output
    attn_kernel<CH2, DD2, false><<<BB * NN, CH2>>>(p_h2, p_s2, p_d2, b2, out);
}